// round 2
// baseline (speedup 1.0000x reference)
#include <cuda_runtime.h>
#include <math.h>

// DoMINO point-MLP: 983040 (point,neighbor) items,
// 33 -> 64 (gelu, exact erf) -> 32 (gelu) -> 8 (tanh), masked sum over P=10,
// output (8, 64, 48, 32) fp32 = out[c*N + n].

namespace {
constexpr int N_PTS = 98304;   // 64*48*32
constexpr int NB    = 10;      // neighbors
// shared layout (floats); all offsets even -> 8B/16B aligned views OK
constexpr int OFF_W1 = 0;      // 33*64 = 2112
constexpr int OFF_B1 = 2112;   // 64
constexpr int OFF_W2 = 2176;   // 64*32 = 2048
constexpr int OFF_B2 = 4224;   // 32
constexpr int OFF_W3 = 4256;   // 32*8 = 256
constexpr int OFF_B3 = 4512;   // 8
constexpr int OFF_FR = 4520;   // 5 (+3 pad)
constexpr int SM_TOT = 4528;
}

typedef unsigned long long u64;

__device__ __forceinline__ u64 pk2(float x, float y) {
    u64 r;
    asm("mov.b64 %0, {%1, %2};" : "=l"(r) : "f"(x), "f"(y));
    return r;
}
__device__ __forceinline__ void up2(u64 a, float& x, float& y) {
    asm("mov.b64 {%0, %1}, %2;" : "=f"(x), "=f"(y) : "l"(a));
}
// packed dual fp32 FMA: d = a*b + d (exact fp32 on both halves)
__device__ __forceinline__ void fma2(u64& d, u64 a, u64 b) {
    asm("fma.rn.f32x2 %0, %1, %2, %0;" : "+l"(d) : "l"(a), "l"(b));
}
__device__ __forceinline__ float gelu_exact(float v) {
    return 0.5f * v * (1.0f + erff(v * 0.70710678118654752440f));
}

__global__ void __launch_bounds__(128)
domino_kernel(const float* __restrict__ x,
              const float* __restrict__ freqs,
              const float* __restrict__ W1, const float* __restrict__ b1,
              const float* __restrict__ W2, const float* __restrict__ b2,
              const float* __restrict__ W3, const float* __restrict__ b3,
              float* __restrict__ out)
{
    __shared__ __align__(16) float sm[SM_TOT];

    // stage weights/biases/freqs into shared (broadcast source for the block)
    for (int i = threadIdx.x; i < 2112; i += blockDim.x) sm[OFF_W1 + i] = W1[i];
    for (int i = threadIdx.x; i < 64;   i += blockDim.x) sm[OFF_B1 + i] = b1[i];
    for (int i = threadIdx.x; i < 2048; i += blockDim.x) sm[OFF_W2 + i] = W2[i];
    for (int i = threadIdx.x; i < 32;   i += blockDim.x) sm[OFF_B2 + i] = b2[i];
    for (int i = threadIdx.x; i < 256;  i += blockDim.x) sm[OFF_W3 + i] = W3[i];
    for (int i = threadIdx.x; i < 8;    i += blockDim.x) sm[OFF_B3 + i] = b3[i];
    for (int i = threadIdx.x; i < 8;    i += blockDim.x) sm[OFF_FR + i] = (i < 5) ? freqs[i] : 0.0f;
    __syncthreads();

    const int n = blockIdx.x * blockDim.x + threadIdx.x;   // grid exact
    const float* xp = x + (size_t)n * NB * 3;

    float fr[5];
#pragma unroll
    for (int m = 0; m < 5; m++) fr[m] = sm[OFF_FR + m];

    const double2* W1v = reinterpret_cast<const double2*>(sm + OFF_W1); // 16/row
    const u64*     b1v = reinterpret_cast<const u64*>(sm + OFF_B1);     // 32 pairs
    const double2* W2v = reinterpret_cast<const double2*>(sm + OFF_W2); // 8/row
    const u64*     b2v = reinterpret_cast<const u64*>(sm + OFF_B2);     // 16 pairs
    const double2* W3v = reinterpret_cast<const double2*>(sm + OFF_W3); // 2/row
    const u64*     b3v = reinterpret_cast<const u64*>(sm + OFF_B3);     // 4 pairs

    float oacc[8];
#pragma unroll
    for (int c = 0; c < 8; c++) oacc[c] = 0.0f;

#pragma unroll 1
    for (int p = 0; p < NB; p++) {
        const float x0 = xp[p * 3 + 0];
        const float x1 = xp[p * 3 + 1];
        const float x2 = xp[p * 3 + 2];
        if (fabsf(x0) <= 1e-6f) continue;   // padded-neighbor mask

        // ---- feature vector (33), constant-indexed registers ----
        float f[33];
        f[0] = x0; f[1] = x1; f[2] = x2;
        const float c3[3] = {x0, x1, x2};
#pragma unroll
        for (int m = 0; m < 5; m++) {
#pragma unroll
            for (int d = 0; d < 3; d++) {
                float s, c;
                __sincosf(c3[d] * fr[m], &s, &c);
                f[3  + m * 3 + d] = s;
                f[18 + m * 3 + d] = c;
            }
        }

        // ---- layer 2 accumulators (32 outputs = 16 packed) ----
        u64 a2[16];
#pragma unroll
        for (int kp = 0; kp < 16; kp++) a2[kp] = b2v[kp];

        // ---- layer 1 in 4 chunks of 16 outputs, streamed into layer 2 ----
#pragma unroll 1
        for (int jc = 0; jc < 4; jc++) {
            u64 a1c[8];
#pragma unroll
            for (int q = 0; q < 8; q++) a1c[q] = b1v[jc * 8 + q];

#pragma unroll
            for (int i = 0; i < 33; i++) {
                u64 ff = pk2(f[i], f[i]);
                const double2* wrow = W1v + i * 16 + jc * 4;
#pragma unroll
                for (int q = 0; q < 4; q++) {
                    double2 w = wrow[q];
                    fma2(a1c[2 * q],     ff, __double_as_longlong(w.x));
                    fma2(a1c[2 * q + 1], ff, __double_as_longlong(w.y));
                }
            }

            // gelu the 16 chunk outputs and accumulate into layer 2
#pragma unroll
            for (int q = 0; q < 8; q++) {
                float u, v;
                up2(a1c[q], u, v);
                const float hu = gelu_exact(u);
                const float hv = gelu_exact(v);
                const int j0 = jc * 16 + 2 * q;
                const double2* w2a = W2v + (size_t)j0 * 8;
                const double2* w2b = w2a + 8;
                u64 fu = pk2(hu, hu);
                u64 fv = pk2(hv, hv);
#pragma unroll
                for (int kq = 0; kq < 8; kq++) {
                    double2 wa = w2a[kq];
                    fma2(a2[2 * kq],     fu, __double_as_longlong(wa.x));
                    fma2(a2[2 * kq + 1], fu, __double_as_longlong(wa.y));
                }
#pragma unroll
                for (int kq = 0; kq < 8; kq++) {
                    double2 wb = w2b[kq];
                    fma2(a2[2 * kq],     fv, __double_as_longlong(wb.x));
                    fma2(a2[2 * kq + 1], fv, __double_as_longlong(wb.y));
                }
            }
        }

        // ---- layer 3: consume a2 pairwise; h2 never materialized ----
        u64 a3[4];
#pragma unroll
        for (int cp = 0; cp < 4; cp++) a3[cp] = b3v[cp];
#pragma unroll
        for (int q = 0; q < 16; q++) {
            float u, v;
            up2(a2[q], u, v);
            const float hu = gelu_exact(u);
            const float hv = gelu_exact(v);
            const int k0 = 2 * q;
            u64 fu = pk2(hu, hu);
            u64 fv = pk2(hv, hv);
#pragma unroll
            for (int cq = 0; cq < 2; cq++) {
                double2 wa = W3v[(k0)     * 2 + cq];
                double2 wb = W3v[(k0 + 1) * 2 + cq];
                fma2(a3[2 * cq],     fu, __double_as_longlong(wa.x));
                fma2(a3[2 * cq + 1], fu, __double_as_longlong(wa.y));
                fma2(a3[2 * cq],     fv, __double_as_longlong(wb.x));
                fma2(a3[2 * cq + 1], fv, __double_as_longlong(wb.y));
            }
        }
#pragma unroll
        for (int cp = 0; cp < 4; cp++) {
            float u, v;
            up2(a3[cp], u, v);
            oacc[2 * cp]     += tanhf(u);
            oacc[2 * cp + 1] += tanhf(v);
        }
    }

    // output layout: (8, 64, 48, 32) -> out[c * N + n]
#pragma unroll
    for (int c = 0; c < 8; c++) out[(size_t)c * N_PTS + n] = oacc[c];
}

extern "C" void kernel_launch(void* const* d_in, const int* in_sizes, int n_in,
                              void* d_out, int out_size)
{
    (void)in_sizes; (void)n_in; (void)out_size;
    const float* x     = (const float*)d_in[0];
    // d_in[1] = grid : unused by the reference math
    const float* freqs = (const float*)d_in[2];
    const float* W1    = (const float*)d_in[3];
    const float* b1    = (const float*)d_in[4];
    const float* W2    = (const float*)d_in[5];
    const float* b2    = (const float*)d_in[6];
    const float* W3    = (const float*)d_in[7];
    const float* b3    = (const float*)d_in[8];

    domino_kernel<<<N_PTS / 128, 128>>>(x, freqs, W1, b1, W2, b2, W3, b3,
                                        (float*)d_out);
}

// round 3
// speedup vs baseline: 1.3184x; 1.3184x over previous
#include <cuda_runtime.h>
#include <math.h>

// DoMINO point-MLP: 983040 (point,neighbor) items,
// 33 -> 64 (gelu, exact erf) -> 32 (gelu) -> 8 (tanh), masked sum over P=10,
// output (8, 64, 48, 32) fp32 = out[c*N + n].

namespace {
constexpr int N_PTS = 98304;   // 64*48*32
constexpr int NB    = 10;      // neighbors
// shared layout (floats); all offsets even -> 8B/16B aligned views OK
constexpr int OFF_W1 = 0;      // 33*64 = 2112
constexpr int OFF_B1 = 2112;   // 64
constexpr int OFF_W2 = 2176;   // 64*32 = 2048
constexpr int OFF_B2 = 4224;   // 32
constexpr int OFF_W3 = 4256;   // 32*8 = 256
constexpr int OFF_B3 = 4512;   // 8
constexpr int OFF_FR = 4520;   // 5 (+3 pad)
constexpr int SM_TOT = 4528;
}

typedef unsigned long long u64;

__device__ __forceinline__ u64 pk2(float x, float y) {
    u64 r;
    asm("mov.b64 %0, {%1, %2};" : "=l"(r) : "f"(x), "f"(y));
    return r;
}
__device__ __forceinline__ void up2(u64 a, float& x, float& y) {
    asm("mov.b64 {%0, %1}, %2;" : "=f"(x), "=f"(y) : "l"(a));
}
// packed dual fp32 FMA: d = a*b + d (exact fp32 on both halves)
__device__ __forceinline__ void fma2(u64& d, u64 a, u64 b) {
    asm("fma.rn.f32x2 %0, %1, %2, %0;" : "+l"(d) : "l"(a), "l"(b));
}
__device__ __forceinline__ float gelu_exact(float v) {
    return 0.5f * v * (1.0f + erff(v * 0.70710678118654752440f));
}
// fast accurate tanh: (e^2x - 1)/(e^2x + 1), clamped so e never overflows.
__device__ __forceinline__ float fast_tanh(float v) {
    float c = fminf(fmaxf(v, -15.0f), 15.0f);
    float e = __expf(2.0f * c);
    return __fdividef(e - 1.0f, e + 1.0f);
}

__global__ void __launch_bounds__(128, 4)
domino_kernel(const float* __restrict__ x,
              const float* __restrict__ freqs,
              const float* __restrict__ W1, const float* __restrict__ b1,
              const float* __restrict__ W2, const float* __restrict__ b2,
              const float* __restrict__ W3, const float* __restrict__ b3,
              float* __restrict__ out)
{
    __shared__ __align__(16) float sm[SM_TOT];

    // stage weights/biases/freqs into shared (broadcast source for the block)
    for (int i = threadIdx.x; i < 2112; i += blockDim.x) sm[OFF_W1 + i] = W1[i];
    for (int i = threadIdx.x; i < 64;   i += blockDim.x) sm[OFF_B1 + i] = b1[i];
    for (int i = threadIdx.x; i < 2048; i += blockDim.x) sm[OFF_W2 + i] = W2[i];
    for (int i = threadIdx.x; i < 32;   i += blockDim.x) sm[OFF_B2 + i] = b2[i];
    for (int i = threadIdx.x; i < 256;  i += blockDim.x) sm[OFF_W3 + i] = W3[i];
    for (int i = threadIdx.x; i < 8;    i += blockDim.x) sm[OFF_B3 + i] = b3[i];
    for (int i = threadIdx.x; i < 8;    i += blockDim.x) sm[OFF_FR + i] = (i < 5) ? freqs[i] : 0.0f;
    __syncthreads();

    const int n = blockIdx.x * blockDim.x + threadIdx.x;   // grid exact
    const float* xp = x + (size_t)n * NB * 3;

    float fr[5];
#pragma unroll
    for (int m = 0; m < 5; m++) fr[m] = sm[OFF_FR + m];

    const double2* W1v = reinterpret_cast<const double2*>(sm + OFF_W1); // 16/row
    const u64*     b1v = reinterpret_cast<const u64*>(sm + OFF_B1);     // 32 pairs
    const double2* W2v = reinterpret_cast<const double2*>(sm + OFF_W2); // 8/row
    const u64*     b2v = reinterpret_cast<const u64*>(sm + OFF_B2);     // 16 pairs
    const double2* W3v = reinterpret_cast<const double2*>(sm + OFF_W3); // 2/row
    const u64*     b3v = reinterpret_cast<const u64*>(sm + OFF_B3);     // 4 pairs

    float oacc[8];
#pragma unroll
    for (int c = 0; c < 8; c++) oacc[c] = 0.0f;

#pragma unroll 1
    for (int p = 0; p < NB; p++) {
        const float x0 = xp[p * 3 + 0];
        const float x1 = xp[p * 3 + 1];
        const float x2 = xp[p * 3 + 2];
        if (fabsf(x0) <= 1e-6f) continue;   // padded-neighbor mask

        // ---- feature vector (33), constant-indexed registers ----
        float f[33];
        f[0] = x0; f[1] = x1; f[2] = x2;
        const float c3[3] = {x0, x1, x2};
#pragma unroll
        for (int m = 0; m < 5; m++) {
#pragma unroll
            for (int d = 0; d < 3; d++) {
                float s, c;
                __sincosf(c3[d] * fr[m], &s, &c);
                f[3  + m * 3 + d] = s;
                f[18 + m * 3 + d] = c;
            }
        }

        // ---- layer 2 accumulators (32 outputs = 16 packed) ----
        u64 a2[16];
#pragma unroll
        for (int kp = 0; kp < 16; kp++) a2[kp] = b2v[kp];

        // ---- layer 1 in 4 chunks of 16 outputs, streamed into layer 2 ----
#pragma unroll 1
        for (int jc = 0; jc < 4; jc++) {
            u64 a1c[8];
#pragma unroll
            for (int q = 0; q < 8; q++) a1c[q] = b1v[jc * 8 + q];

#pragma unroll
            for (int i = 0; i < 33; i++) {
                u64 ff = pk2(f[i], f[i]);
                const double2* wrow = W1v + i * 16 + jc * 4;
#pragma unroll
                for (int q = 0; q < 4; q++) {
                    double2 w = wrow[q];
                    fma2(a1c[2 * q],     ff, __double_as_longlong(w.x));
                    fma2(a1c[2 * q + 1], ff, __double_as_longlong(w.y));
                }
            }

            // gelu the 16 chunk outputs and accumulate into layer 2
#pragma unroll
            for (int q = 0; q < 8; q++) {
                float u, v;
                up2(a1c[q], u, v);
                const float hu = gelu_exact(u);
                const float hv = gelu_exact(v);
                const int j0 = jc * 16 + 2 * q;
                const double2* w2a = W2v + (size_t)j0 * 8;
                const double2* w2b = w2a + 8;
                u64 fu = pk2(hu, hu);
                u64 fv = pk2(hv, hv);
#pragma unroll
                for (int kq = 0; kq < 8; kq++) {
                    double2 wa = w2a[kq];
                    fma2(a2[2 * kq],     fu, __double_as_longlong(wa.x));
                    fma2(a2[2 * kq + 1], fu, __double_as_longlong(wa.y));
                }
#pragma unroll
                for (int kq = 0; kq < 8; kq++) {
                    double2 wb = w2b[kq];
                    fma2(a2[2 * kq],     fv, __double_as_longlong(wb.x));
                    fma2(a2[2 * kq + 1], fv, __double_as_longlong(wb.y));
                }
            }
        }

        // ---- layer 3: consume a2 pairwise; h2 never materialized ----
        u64 a3[4];
#pragma unroll
        for (int cp = 0; cp < 4; cp++) a3[cp] = b3v[cp];
#pragma unroll
        for (int q = 0; q < 16; q++) {
            float u, v;
            up2(a2[q], u, v);
            const float hu = gelu_exact(u);
            const float hv = gelu_exact(v);
            const int k0 = 2 * q;
            u64 fu = pk2(hu, hu);
            u64 fv = pk2(hv, hv);
#pragma unroll
            for (int cq = 0; cq < 2; cq++) {
                double2 wa = W3v[(k0)     * 2 + cq];
                double2 wb = W3v[(k0 + 1) * 2 + cq];
                fma2(a3[2 * cq],     fu, __double_as_longlong(wa.x));
                fma2(a3[2 * cq + 1], fu, __double_as_longlong(wa.y));
                fma2(a3[2 * cq],     fv, __double_as_longlong(wb.x));
                fma2(a3[2 * cq + 1], fv, __double_as_longlong(wb.y));
            }
        }
#pragma unroll
        for (int cp = 0; cp < 4; cp++) {
            float u, v;
            up2(a3[cp], u, v);
            oacc[2 * cp]     += fast_tanh(u);
            oacc[2 * cp + 1] += fast_tanh(v);
        }
    }

    // output layout: (8, 64, 48, 32) -> out[c * N + n]
#pragma unroll
    for (int c = 0; c < 8; c++) out[(size_t)c * N_PTS + n] = oacc[c];
}

extern "C" void kernel_launch(void* const* d_in, const int* in_sizes, int n_in,
                              void* d_out, int out_size)
{
    (void)in_sizes; (void)n_in; (void)out_size;
    const float* x     = (const float*)d_in[0];
    // d_in[1] = grid : unused by the reference math
    const float* freqs = (const float*)d_in[2];
    const float* W1    = (const float*)d_in[3];
    const float* b1    = (const float*)d_in[4];
    const float* W2    = (const float*)d_in[5];
    const float* b2    = (const float*)d_in[6];
    const float* W3    = (const float*)d_in[7];
    const float* b3    = (const float*)d_in[8];

    domino_kernel<<<N_PTS / 128, 128>>>(x, freqs, W1, b1, W2, b2, W3, b3,
                                        (float*)d_out);
}

// round 4
// speedup vs baseline: 2.0184x; 1.5310x over previous
#include <cuda_runtime.h>
#include <math.h>

// DoMINO point-MLP, one thread per (point, neighbor) item.
// 33 -> 64 (gelu, exact-erf quality) -> 32 (gelu) -> 8 (tanh),
// masked, reduced over P=10 via global RED; out (8,64,48,32) fp32.

namespace {
constexpr int N_PTS = 98304;       // 64*48*32
constexpr int NB    = 10;
constexpr int NITEM = N_PTS * NB;  // 983040
// shared layout (floats); all offsets even -> 8B/16B aligned views OK
constexpr int OFF_W1 = 0;      // 33*64 = 2112
constexpr int OFF_B1 = 2112;   // 64
constexpr int OFF_W2 = 2176;   // 64*32 = 2048
constexpr int OFF_B2 = 4224;   // 32
constexpr int OFF_W3 = 4256;   // 32*8 = 256
constexpr int OFF_B3 = 4512;   // 8
constexpr int OFF_FR = 4520;   // 5 (+3 pad)
constexpr int SM_TOT = 4528;
}

typedef unsigned long long u64;

__device__ __forceinline__ u64 pk2(float x, float y) {
    u64 r;
    asm("mov.b64 %0, {%1, %2};" : "=l"(r) : "f"(x), "f"(y));
    return r;
}
__device__ __forceinline__ void up2(u64 a, float& x, float& y) {
    asm("mov.b64 {%0, %1}, %2;" : "=f"(x), "=f"(y) : "l"(a));
}
// packed dual fp32 FMA: d = a*b + d (exact fp32 on both halves)
__device__ __forceinline__ void fma2(u64& d, u64 a, u64 b) {
    asm("fma.rn.f32x2 %0, %1, %2, %0;" : "+l"(d) : "l"(a), "l"(b));
}

// GELU with Abramowitz-Stegun 7.1.26 erf (|err| <= 1.5e-7).
__device__ __forceinline__ float gelu_fast(float v) {
    const float z  = v * 0.70710678118654752440f;
    const float za = fabsf(z);
    float t;
    asm("rcp.approx.f32 %0, %1;" : "=f"(t) : "f"(fmaf(0.3275911f, za, 1.0f)));
    float poly = fmaf(1.061405429f, t, -1.453152027f);
    poly = fmaf(poly, t, 1.421413741f);
    poly = fmaf(poly, t, -0.284496736f);
    poly = fmaf(poly, t, 0.254829592f);
    poly *= t;
    const float e  = __expf(-za * za);
    float erfa = fmaf(-poly, e, 1.0f);          // erf(|z|)
    float erfz = copysignf(erfa, z);
    return 0.5f * v * (1.0f + erfz);
}
// fast tanh: (e^2x - 1)/(e^2x + 1), clamped so e never overflows.
__device__ __forceinline__ float fast_tanh(float v) {
    float c = fminf(fmaxf(v, -15.0f), 15.0f);
    float e = __expf(2.0f * c);
    return __fdividef(e - 1.0f, e + 1.0f);
}

__global__ void zero_out_kernel(float* __restrict__ out, int n4) {
    int i = blockIdx.x * blockDim.x + threadIdx.x;
    if (i < n4) reinterpret_cast<float4*>(out)[i] = make_float4(0.f, 0.f, 0.f, 0.f);
}

__global__ void __launch_bounds__(128, 5)
domino_kernel(const float* __restrict__ x,
              const float* __restrict__ freqs,
              const float* __restrict__ W1, const float* __restrict__ b1,
              const float* __restrict__ W2, const float* __restrict__ b2,
              const float* __restrict__ W3, const float* __restrict__ b3,
              float* __restrict__ out)
{
    __shared__ __align__(16) float sm[SM_TOT];

    // stage weights/biases/freqs into shared (broadcast source for the block)
    for (int i = threadIdx.x; i < 2112; i += blockDim.x) sm[OFF_W1 + i] = W1[i];
    for (int i = threadIdx.x; i < 64;   i += blockDim.x) sm[OFF_B1 + i] = b1[i];
    for (int i = threadIdx.x; i < 2048; i += blockDim.x) sm[OFF_W2 + i] = W2[i];
    for (int i = threadIdx.x; i < 32;   i += blockDim.x) sm[OFF_B2 + i] = b2[i];
    for (int i = threadIdx.x; i < 256;  i += blockDim.x) sm[OFF_W3 + i] = W3[i];
    for (int i = threadIdx.x; i < 8;    i += blockDim.x) sm[OFF_B3 + i] = b3[i];
    for (int i = threadIdx.x; i < 8;    i += blockDim.x) sm[OFF_FR + i] = (i < 5) ? freqs[i] : 0.0f;
    __syncthreads();

    const int item = blockIdx.x * blockDim.x + threadIdx.x;   // grid exact
    const int n = item / NB;          // point index
    // coords for this (point, neighbor)
    const float* xp = x + (size_t)item * 3;
    const float x0 = xp[0];
    const float x1 = xp[1];
    const float x2 = xp[2];
    if (fabsf(x0) <= 1e-6f) return;   // padded-neighbor mask (contributes 0)

    const double2* W1v = reinterpret_cast<const double2*>(sm + OFF_W1); // 16/row
    const u64*     b1v = reinterpret_cast<const u64*>(sm + OFF_B1);
    const double2* W2v = reinterpret_cast<const double2*>(sm + OFF_W2); // 8/row
    const u64*     b2v = reinterpret_cast<const u64*>(sm + OFF_B2);
    const double2* W3v = reinterpret_cast<const double2*>(sm + OFF_W3); // 2/row
    const u64*     b3v = reinterpret_cast<const u64*>(sm + OFF_B3);

    // ---- feature vector (33), constant-indexed registers ----
    float f[33];
    f[0] = x0; f[1] = x1; f[2] = x2;
    {
        const float c3[3] = {x0, x1, x2};
#pragma unroll
        for (int m = 0; m < 5; m++) {
            const float frm = sm[OFF_FR + m];
#pragma unroll
            for (int d = 0; d < 3; d++) {
                float s, c;
                __sincosf(c3[d] * frm, &s, &c);
                f[3  + m * 3 + d] = s;
                f[18 + m * 3 + d] = c;
            }
        }
    }

    // ---- layer 2 accumulators (32 outputs = 16 packed) ----
    u64 a2[16];
#pragma unroll
    for (int kp = 0; kp < 16; kp++) a2[kp] = b2v[kp];

    // ---- layer 1 in 4 chunks of 16 outputs, streamed into layer 2 ----
#pragma unroll 1
    for (int jc = 0; jc < 4; jc++) {
        u64 a1c[8];
#pragma unroll
        for (int q = 0; q < 8; q++) a1c[q] = b1v[jc * 8 + q];

#pragma unroll
        for (int i = 0; i < 33; i++) {
            u64 ff = pk2(f[i], f[i]);
            const double2* wrow = W1v + i * 16 + jc * 4;
#pragma unroll
            for (int q = 0; q < 4; q++) {
                double2 w = wrow[q];
                fma2(a1c[2 * q],     ff, __double_as_longlong(w.x));
                fma2(a1c[2 * q + 1], ff, __double_as_longlong(w.y));
            }
        }

        // gelu the 16 chunk outputs and accumulate into layer 2
#pragma unroll
        for (int q = 0; q < 8; q++) {
            float u, v;
            up2(a1c[q], u, v);
            const float hu = gelu_fast(u);
            const float hv = gelu_fast(v);
            const int j0 = jc * 16 + 2 * q;
            const double2* w2a = W2v + (size_t)j0 * 8;
            const double2* w2b = w2a + 8;
            u64 fu = pk2(hu, hu);
            u64 fv = pk2(hv, hv);
#pragma unroll
            for (int kq = 0; kq < 8; kq++) {
                double2 wa = w2a[kq];
                fma2(a2[2 * kq],     fu, __double_as_longlong(wa.x));
                fma2(a2[2 * kq + 1], fu, __double_as_longlong(wa.y));
            }
#pragma unroll
            for (int kq = 0; kq < 8; kq++) {
                double2 wb = w2b[kq];
                fma2(a2[2 * kq],     fv, __double_as_longlong(wb.x));
                fma2(a2[2 * kq + 1], fv, __double_as_longlong(wb.y));
            }
        }
    }

    // ---- layer 3: consume a2 pairwise; h2 never materialized ----
    u64 a3[4];
#pragma unroll
    for (int cp = 0; cp < 4; cp++) a3[cp] = b3v[cp];
#pragma unroll
    for (int q = 0; q < 16; q++) {
        float u, v;
        up2(a2[q], u, v);
        const float hu = gelu_fast(u);
        const float hv = gelu_fast(v);
        const int k0 = 2 * q;
        u64 fu = pk2(hu, hu);
        u64 fv = pk2(hv, hv);
#pragma unroll
        for (int cq = 0; cq < 2; cq++) {
            double2 wa = W3v[(k0)     * 2 + cq];
            double2 wb = W3v[(k0 + 1) * 2 + cq];
            fma2(a3[2 * cq],     fu, __double_as_longlong(wa.x));
            fma2(a3[2 * cq + 1], fu, __double_as_longlong(wa.y));
            fma2(a3[2 * cq],     fv, __double_as_longlong(wb.x));
            fma2(a3[2 * cq + 1], fv, __double_as_longlong(wb.y));
        }
    }

    // ---- tanh + reduce over neighbors via global RED ----
#pragma unroll
    for (int cp = 0; cp < 4; cp++) {
        float u, v;
        up2(a3[cp], u, v);
        atomicAdd(&out[(size_t)(2 * cp)     * N_PTS + n], fast_tanh(u));
        atomicAdd(&out[(size_t)(2 * cp + 1) * N_PTS + n], fast_tanh(v));
    }
}

extern "C" void kernel_launch(void* const* d_in, const int* in_sizes, int n_in,
                              void* d_out, int out_size)
{
    (void)in_sizes; (void)n_in; (void)out_size;
    const float* x     = (const float*)d_in[0];
    // d_in[1] = grid : unused by the reference math
    const float* freqs = (const float*)d_in[2];
    const float* W1    = (const float*)d_in[3];
    const float* b1    = (const float*)d_in[4];
    const float* W2    = (const float*)d_in[5];
    const float* b2    = (const float*)d_in[6];
    const float* W3    = (const float*)d_in[7];
    const float* b3    = (const float*)d_in[8];
    float* out = (float*)d_out;

    // zero the output (8 * N_PTS floats = 786432 -> 196608 float4)
    const int n4 = (8 * N_PTS) / 4;
    zero_out_kernel<<<(n4 + 255) / 256, 256>>>(out, n4);

    domino_kernel<<<NITEM / 128, 128>>>(x, freqs, W1, b1, W2, b2, W3, b3, out);
}

// round 6
// speedup vs baseline: 2.4009x; 1.1895x over previous
#include <cuda_runtime.h>
#include <math.h>

// DoMINO point-MLP, TWO (point,neighbor) items per thread (same point),
// sharing every weight load between the two items.
// 33 -> 64 (gelu) -> 32 (gelu) -> 8 (tanh), masked sum over P=10,
// out (8,64,48,32) fp32, reduced via global RED into pre-zeroed d_out.

namespace {
constexpr int N_PTS = 98304;       // 64*48*32
constexpr int NB    = 10;
constexpr int NITEM = N_PTS * NB;  // 983040
constexpr int NTHRD = NITEM / 2;   // 491520 threads, 2 items each
// shared layout (floats); all offsets even -> 8B/16B aligned views OK
constexpr int OFF_W1 = 0;      // 33*64 = 2112
constexpr int OFF_B1 = 2112;   // 64
constexpr int OFF_W2 = 2176;   // 64*32 = 2048
constexpr int OFF_B2 = 4224;   // 32
constexpr int OFF_W3 = 4256;   // 32*8 = 256
constexpr int OFF_B3 = 4512;   // 8
constexpr int OFF_FR = 4520;   // 5 (+3 pad)
constexpr int SM_TOT = 4528;
}

typedef unsigned long long u64;

__device__ __forceinline__ u64 pk2(float x, float y) {
    u64 r;
    asm("mov.b64 %0, {%1, %2};" : "=l"(r) : "f"(x), "f"(y));
    return r;
}
__device__ __forceinline__ void up2(u64 a, float& x, float& y) {
    asm("mov.b64 {%0, %1}, %2;" : "=f"(x), "=f"(y) : "l"(a));
}
// packed dual fp32 FMA: d = a*b + d (exact fp32 on both halves)
__device__ __forceinline__ void fma2(u64& d, u64 a, u64 b) {
    asm("fma.rn.f32x2 %0, %1, %2, %0;" : "+l"(d) : "l"(a), "l"(b));
}

// GELU with Abramowitz-Stegun 7.1.26 erf (|err| <= 1.5e-7).
__device__ __forceinline__ float gelu_fast(float v) {
    const float z  = v * 0.70710678118654752440f;
    const float za = fabsf(z);
    float t;
    asm("rcp.approx.f32 %0, %1;" : "=f"(t) : "f"(fmaf(0.3275911f, za, 1.0f)));
    float poly = fmaf(1.061405429f, t, -1.453152027f);
    poly = fmaf(poly, t, 1.421413741f);
    poly = fmaf(poly, t, -0.284496736f);
    poly = fmaf(poly, t, 0.254829592f);
    poly *= t;
    const float e  = __expf(-za * za);
    float erfa = fmaf(-poly, e, 1.0f);          // erf(|z|)
    float erfz = copysignf(erfa, z);
    return 0.5f * v * (1.0f + erfz);
}
// fast tanh: (e^2x - 1)/(e^2x + 1), clamped so e never overflows.
__device__ __forceinline__ float fast_tanh(float v) {
    float c = fminf(fmaxf(v, -15.0f), 15.0f);
    float e = __expf(2.0f * c);
    return __fdividef(e - 1.0f, e + 1.0f);
}

__global__ void zero_out_kernel(float* __restrict__ out, int n4) {
    int i = blockIdx.x * blockDim.x + threadIdx.x;
    if (i < n4) reinterpret_cast<float4*>(out)[i] = make_float4(0.f, 0.f, 0.f, 0.f);
}

__global__ void __launch_bounds__(128, 3)
domino_kernel(const float* __restrict__ x,
              const float* __restrict__ freqs,
              const float* __restrict__ W1, const float* __restrict__ b1,
              const float* __restrict__ W2, const float* __restrict__ b2,
              const float* __restrict__ W3, const float* __restrict__ b3,
              float* __restrict__ out)
{
    __shared__ __align__(16) float sm[SM_TOT];

    // stage weights/biases/freqs into shared (broadcast source for the block)
    for (int i = threadIdx.x; i < 2112; i += blockDim.x) sm[OFF_W1 + i] = W1[i];
    for (int i = threadIdx.x; i < 64;   i += blockDim.x) sm[OFF_B1 + i] = b1[i];
    for (int i = threadIdx.x; i < 2048; i += blockDim.x) sm[OFF_W2 + i] = W2[i];
    for (int i = threadIdx.x; i < 32;   i += blockDim.x) sm[OFF_B2 + i] = b2[i];
    for (int i = threadIdx.x; i < 256;  i += blockDim.x) sm[OFF_W3 + i] = W3[i];
    for (int i = threadIdx.x; i < 8;    i += blockDim.x) sm[OFF_B3 + i] = b3[i];
    for (int i = threadIdx.x; i < 8;    i += blockDim.x) sm[OFF_FR + i] = (i < 5) ? freqs[i] : 0.0f;
    __syncthreads();

    const int t = blockIdx.x * blockDim.x + threadIdx.x;   // grid exact
    const int n = t / 5;                                   // output point index

    // items 2t and 2t+1 (same point): 6 consecutive floats, 8B aligned
    const float2* xv = reinterpret_cast<const float2*>(x + (size_t)t * 6);
    const float2 v0 = xv[0], v1 = xv[1], v2 = xv[2];
    const float xa0 = v0.x, xa1 = v0.y, xa2 = v1.x;
    const float xb0 = v1.y, xb1 = v2.x, xb2 = v2.y;
    const float ma = (fabsf(xa0) > 1e-6f) ? 1.0f : 0.0f;   // padded-neighbor masks
    const float mb = (fabsf(xb0) > 1e-6f) ? 1.0f : 0.0f;

    // double2 = 4 floats. Row sizes in double2: W1 row(64f)=16, W2 row(32f)=8, W3 row(8f)=2.
    const double2* W1v = reinterpret_cast<const double2*>(sm + OFF_W1);
    const u64*     b1v = reinterpret_cast<const u64*>(sm + OFF_B1);
    const double2* W2v = reinterpret_cast<const double2*>(sm + OFF_W2);
    const u64*     b2v = reinterpret_cast<const u64*>(sm + OFF_B2);
    const double2* W3v = reinterpret_cast<const double2*>(sm + OFF_W3);
    const u64*     b3v = reinterpret_cast<const u64*>(sm + OFF_B3);

    // ---- feature vectors (33 each), constant-indexed registers ----
    float fa[33], fb[33];
    fa[0] = xa0; fa[1] = xa1; fa[2] = xa2;
    fb[0] = xb0; fb[1] = xb1; fb[2] = xb2;
    {
        const float ca[3] = {xa0, xa1, xa2};
        const float cb[3] = {xb0, xb1, xb2};
#pragma unroll
        for (int m = 0; m < 5; m++) {
            const float frm = sm[OFF_FR + m];
#pragma unroll
            for (int d = 0; d < 3; d++) {
                float s, c;
                __sincosf(ca[d] * frm, &s, &c);
                fa[3  + m * 3 + d] = s;
                fa[18 + m * 3 + d] = c;
                __sincosf(cb[d] * frm, &s, &c);
                fb[3  + m * 3 + d] = s;
                fb[18 + m * 3 + d] = c;
            }
        }
    }

    // ---- layer 2 accumulators (32 outputs = 16 packed) per item ----
    u64 a2a[16], a2b[16];
#pragma unroll
    for (int kp = 0; kp < 16; kp++) { a2a[kp] = b2v[kp]; a2b[kp] = a2a[kp]; }

    // ---- layer 1 in 4 chunks of 16 outputs, streamed into layer 2 ----
#pragma unroll 1
    for (int jc = 0; jc < 4; jc++) {
        u64 c1a[8], c1b[8];
#pragma unroll
        for (int q = 0; q < 8; q++) { c1a[q] = b1v[jc * 8 + q]; c1b[q] = c1a[q]; }

#pragma unroll
        for (int i = 0; i < 33; i++) {
            const u64 ffa = pk2(fa[i], fa[i]);
            const u64 ffb = pk2(fb[i], fb[i]);
            const double2* wrow = W1v + i * 16 + jc * 4;
#pragma unroll
            for (int q = 0; q < 4; q++) {
                const double2 w = wrow[q];           // one LDS.128, serves both items
                const u64 wx = __double_as_longlong(w.x);
                const u64 wy = __double_as_longlong(w.y);
                fma2(c1a[2 * q],     ffa, wx);
                fma2(c1a[2 * q + 1], ffa, wy);
                fma2(c1b[2 * q],     ffb, wx);
                fma2(c1b[2 * q + 1], ffb, wy);
            }
        }

        // gelu the 16 chunk outputs of each item; stream into layer 2
#pragma unroll
        for (int q = 0; q < 8; q++) {
            float ua, va, ub, vb;
            up2(c1a[q], ua, va);
            up2(c1b[q], ub, vb);
            const float gau = gelu_fast(ua), gav = gelu_fast(va);
            const float gbu = gelu_fast(ub), gbv = gelu_fast(vb);
            const u64 hau = pk2(gau, gau);
            const u64 hav = pk2(gav, gav);
            const u64 hbu = pk2(gbu, gbu);
            const u64 hbv = pk2(gbv, gbv);
            const int j0 = jc * 16 + 2 * q;
            const double2* w2a = W2v + (size_t)j0 * 8;   // row j0 (8 double2 = 32 floats)
            const double2* w2b = w2a + 8;                // row j0+1
#pragma unroll
            for (int kq = 0; kq < 8; kq++) {
                const double2 wa = w2a[kq];              // one LDS.128 serves both items
                const u64 wax = __double_as_longlong(wa.x);
                const u64 way = __double_as_longlong(wa.y);
                fma2(a2a[2 * kq],     hau, wax);
                fma2(a2a[2 * kq + 1], hau, way);
                fma2(a2b[2 * kq],     hbu, wax);
                fma2(a2b[2 * kq + 1], hbu, way);
                const double2 wb = w2b[kq];
                const u64 wbx = __double_as_longlong(wb.x);
                const u64 wby = __double_as_longlong(wb.y);
                fma2(a2a[2 * kq],     hav, wbx);
                fma2(a2a[2 * kq + 1], hav, wby);
                fma2(a2b[2 * kq],     hbv, wbx);
                fma2(a2b[2 * kq + 1], hbv, wby);
            }
        }
    }

    // ---- layer 3: consume a2 pairwise; h2 never materialized ----
    u64 a3a[4], a3b[4];
#pragma unroll
    for (int cp = 0; cp < 4; cp++) { a3a[cp] = b3v[cp]; a3b[cp] = a3a[cp]; }
#pragma unroll
    for (int q = 0; q < 16; q++) {
        float ua, va, ub, vb;
        up2(a2a[q], ua, va);
        up2(a2b[q], ub, vb);
        const float gau = gelu_fast(ua), gav = gelu_fast(va);
        const float gbu = gelu_fast(ub), gbv = gelu_fast(vb);
        const u64 hau = pk2(gau, gau);
        const u64 hav = pk2(gav, gav);
        const u64 hbu = pk2(gbu, gbu);
        const u64 hbv = pk2(gbv, gbv);
        const int k0 = 2 * q;
        const double2* w3a = W3v + (size_t)k0 * 2;   // row k0 (2 double2 = 8 floats)
        const double2* w3b = w3a + 2;                // row k0+1
#pragma unroll
        for (int cq = 0; cq < 2; cq++) {
            const double2 wa = w3a[cq];
            const double2 wb = w3b[cq];
            const u64 wax = __double_as_longlong(wa.x);
            const u64 way = __double_as_longlong(wa.y);
            const u64 wbx = __double_as_longlong(wb.x);
            const u64 wby = __double_as_longlong(wb.y);
            fma2(a3a[2 * cq],     hau, wax);
            fma2(a3a[2 * cq + 1], hau, way);
            fma2(a3a[2 * cq],     hav, wbx);
            fma2(a3a[2 * cq + 1], hav, wby);
            fma2(a3b[2 * cq],     hbu, wax);
            fma2(a3b[2 * cq + 1], hbu, way);
            fma2(a3b[2 * cq],     hbv, wbx);
            fma2(a3b[2 * cq + 1], hbv, wby);
        }
    }

    // ---- tanh, mask, combine the two items, reduce via global RED ----
#pragma unroll
    for (int cp = 0; cp < 4; cp++) {
        float ua, va, ub, vb;
        up2(a3a[cp], ua, va);
        up2(a3b[cp], ub, vb);
        const float r0 = ma * fast_tanh(ua) + mb * fast_tanh(ub);
        const float r1 = ma * fast_tanh(va) + mb * fast_tanh(vb);
        atomicAdd(&out[(size_t)(2 * cp)     * N_PTS + n], r0);
        atomicAdd(&out[(size_t)(2 * cp + 1) * N_PTS + n], r1);
    }
}

extern "C" void kernel_launch(void* const* d_in, const int* in_sizes, int n_in,
                              void* d_out, int out_size)
{
    (void)in_sizes; (void)n_in; (void)out_size;
    const float* x     = (const float*)d_in[0];
    // d_in[1] = grid : unused by the reference math
    const float* freqs = (const float*)d_in[2];
    const float* W1    = (const float*)d_in[3];
    const float* b1    = (const float*)d_in[4];
    const float* W2    = (const float*)d_in[5];
    const float* b2    = (const float*)d_in[6];
    const float* W3    = (const float*)d_in[7];
    const float* b3    = (const float*)d_in[8];
    float* out = (float*)d_out;

    // zero the output (8 * N_PTS floats = 786432 -> 196608 float4)
    const int n4 = (8 * N_PTS) / 4;
    zero_out_kernel<<<(n4 + 255) / 256, 256>>>(out, n4);

    domino_kernel<<<NTHRD / 128, 128>>>(x, freqs, W1, b1, W2, b2, W3, b3, out);
}